// round 9
// baseline (speedup 1.0000x reference)
#include <cuda_runtime.h>
#include <cuda_bf16.h>
#include <math.h>
#include <stdint.h>

// Problem constants
#define BATCH 2
#define SEQ   2048
#define DMODEL 2048
#define NHEADS 16
#define DHEAD 128
#define MROWS (BATCH*SEQ)        // 4096
#define NQKV  (3*DMODEL)         // 6144
#define NBH   (BATCH*NHEADS)     // 32

// ---------------------------------------------------------------------------
// Scratch (device globals; no runtime allocation allowed).
// ---------------------------------------------------------------------------
__device__ float g_q [ (size_t)MROWS * DMODEL ];                  // q pre-norm fp32
__device__ __nv_bfloat16 g_xh [ (size_t)MROWS * DMODEL ];
__device__ __nv_bfloat16 g_xl [ (size_t)MROWS * DMODEL ];
__device__ __nv_bfloat16 g_Wqh[ (size_t)NQKV  * DMODEL ];
__device__ __nv_bfloat16 g_Wql[ (size_t)NQKV  * DMODEL ];
__device__ __nv_bfloat16 g_Woh[ (size_t)DMODEL* DMODEL ];
__device__ __nv_bfloat16 g_Wol[ (size_t)DMODEL* DMODEL ];
__device__ __nv_bfloat16 g_qh [ (size_t)MROWS * DMODEL ];
__device__ __nv_bfloat16 g_ql [ (size_t)MROWS * DMODEL ];
__device__ __nv_bfloat16 g_kh [ (size_t)MROWS * DMODEL ];
__device__ __nv_bfloat16 g_kl [ (size_t)MROWS * DMODEL ];
__device__ __nv_bfloat16 g_vh [ (size_t)MROWS * DMODEL ];
__device__ __nv_bfloat16 g_vl [ (size_t)MROWS * DMODEL ];
__device__ __nv_bfloat16 g_zh [ (size_t)MROWS * DMODEL ];
__device__ __nv_bfloat16 g_zl [ (size_t)MROWS * DMODEL ];
// attention scratch
__device__ float         g_s  [ (size_t)NBH * SEQ * SEQ ];        // scores fp32 (536MB)
__device__ __nv_bfloat16 g_ph [ (size_t)NBH * SEQ * SEQ ];        // probs hi
__device__ __nv_bfloat16 g_pl [ (size_t)NBH * SEQ * SEQ ];        // probs lo

// ---------------------------------------------------------------------------
// helpers
// ---------------------------------------------------------------------------
__device__ __forceinline__ uint32_t smem_u32(const void* p) {
    return (uint32_t)__cvta_generic_to_shared(p);
}
__device__ __forceinline__ void cp16(void* dst, const void* src) {
    asm volatile("cp.async.cg.shared.global [%0], [%1], 16;"
                 :: "r"(smem_u32(dst)), "l"(src));
}
__device__ __forceinline__ void cp_commit() { asm volatile("cp.async.commit_group;"); }
template<int N> __device__ __forceinline__ void cp_wait() {
    asm volatile("cp.async.wait_group %0;" :: "n"(N));
}
__device__ __forceinline__ void ldsm_x4(uint32_t addr, uint32_t& r0, uint32_t& r1,
                                        uint32_t& r2, uint32_t& r3) {
    asm volatile("ldmatrix.sync.aligned.m8n8.x4.shared.b16 {%0,%1,%2,%3}, [%4];"
                 : "=r"(r0), "=r"(r1), "=r"(r2), "=r"(r3) : "r"(addr));
}
__device__ __forceinline__ void ldsm_x4_t(uint32_t addr, uint32_t& r0, uint32_t& r1,
                                          uint32_t& r2, uint32_t& r3) {
    asm volatile("ldmatrix.sync.aligned.m8n8.x4.trans.shared.b16 {%0,%1,%2,%3}, [%4];"
                 : "=r"(r0), "=r"(r1), "=r"(r2), "=r"(r3) : "r"(addr));
}
__device__ __forceinline__ void mma16816(float* d, const uint32_t* a, const uint32_t* b) {
    asm volatile(
        "mma.sync.aligned.m16n8k16.row.col.f32.bf16.bf16.f32 "
        "{%0,%1,%2,%3}, {%4,%5,%6,%7}, {%8,%9}, {%0,%1,%2,%3};"
        : "+f"(d[0]), "+f"(d[1]), "+f"(d[2]), "+f"(d[3])
        : "r"(a[0]), "r"(a[1]), "r"(a[2]), "r"(a[3]), "r"(b[0]), "r"(b[1]));
}

// ---------------------------------------------------------------------------
// fp32 -> bf16 hi/lo plane split (elementwise, float4 vectorized)
// ---------------------------------------------------------------------------
__global__ void split_kernel(const float* __restrict__ in,
                             __nv_bfloat16* __restrict__ h,
                             __nv_bfloat16* __restrict__ l, int n4)
{
    int i = blockIdx.x * blockDim.x + threadIdx.x;
    if (i >= n4) return;
    float4 v = ((const float4*)in)[i];
    __nv_bfloat162 h0 = __floats2bfloat162_rn(v.x, v.y);
    __nv_bfloat162 h1 = __floats2bfloat162_rn(v.z, v.w);
    float2 f0 = __bfloat1622float2(h0);
    float2 f1 = __bfloat1622float2(h1);
    __nv_bfloat162 l0 = __floats2bfloat162_rn(v.x - f0.x, v.y - f0.y);
    __nv_bfloat162 l1 = __floats2bfloat162_rn(v.z - f1.x, v.w - f1.y);
    ((__nv_bfloat162*)h)[2*i]   = h0;
    ((__nv_bfloat162*)h)[2*i+1] = h1;
    ((__nv_bfloat162*)l)[2*i]   = l0;
    ((__nv_bfloat162*)l)[2*i+1] = l1;
}

// ---------------------------------------------------------------------------
// bf16x3 GEMM from planes, 3-stage cp.async pipeline.
// C[m,n] = sum_k A[m,k]*B[n,k] + bias[n]
// BM=BN=128, BK=32, 256 threads = 8 warps (2m x 4n), warp tile 64x32.
// mode 0: C0 (ld=N). mode 1: QKV routing; v additionally emits bf16 planes.
// ---------------------------------------------------------------------------
#define GP 40
#define GSTAGES 3
#define GTSZ (128 * GP)

__global__ __launch_bounds__(256, 1)
void gemm_planes(const __nv_bfloat16* __restrict__ Ah, const __nv_bfloat16* __restrict__ Al,
                 const __nv_bfloat16* __restrict__ Bh, const __nv_bfloat16* __restrict__ Bl,
                 const float* __restrict__ bias,
                 float* __restrict__ C0, float* __restrict__ C1, float* __restrict__ C2,
                 __nv_bfloat16* __restrict__ VH, __nv_bfloat16* __restrict__ VL,
                 int M, int N, int K, int mode)
{
    extern __shared__ __nv_bfloat16 smg[];
    __nv_bfloat16* sAh = smg;
    __nv_bfloat16* sAl = sAh + GSTAGES * GTSZ;
    __nv_bfloat16* sBh = sAl + GSTAGES * GTSZ;
    __nv_bfloat16* sBl = sBh + GSTAGES * GTSZ;

    const int tid  = threadIdx.x;
    const int wid  = tid >> 5;
    const int lane = tid & 31;
    const int wm   = wid >> 2;
    const int wn   = wid & 3;
    const int m0   = blockIdx.y * 128;
    const int n0   = blockIdx.x * 128;

    const int lrow = tid >> 1;
    const int lcol = (tid & 1) * 16;

    float acc[4][4][4];
#pragma unroll
    for (int i = 0; i < 4; i++)
#pragma unroll
        for (int j = 0; j < 4; j++)
#pragma unroll
            for (int r = 0; r < 4; r++) acc[i][j][r] = 0.f;

    const int iters = K / 32;

    auto load_tile = [&](int t, int st) {
        size_t ga = (size_t)(m0 + lrow) * K + t * 32 + lcol;
        size_t gb = (size_t)(n0 + lrow) * K + t * 32 + lcol;
        size_t so = (size_t)st * GTSZ + lrow * GP + lcol;
        cp16(sAh + so,     Ah + ga);
        cp16(sAh + so + 8, Ah + ga + 8);
        cp16(sAl + so,     Al + ga);
        cp16(sAl + so + 8, Al + ga + 8);
        cp16(sBh + so,     Bh + gb);
        cp16(sBh + so + 8, Bh + gb + 8);
        cp16(sBl + so,     Bl + gb);
        cp16(sBl + so + 8, Bl + gb + 8);
    };

    load_tile(0, 0); cp_commit();
    load_tile(1, 1); cp_commit();

    for (int it = 0; it < iters; ++it) {
        if (it + 2 < iters) cp_wait<1>(); else cp_wait<0>();
        __syncthreads();
        if (it + 2 < iters) { load_tile(it + 2, (it + 2) % GSTAGES); cp_commit(); }

        const __nv_bfloat16* tAh = sAh + (size_t)(it % GSTAGES) * GTSZ;
        const __nv_bfloat16* tAl = sAl + (size_t)(it % GSTAGES) * GTSZ;
        const __nv_bfloat16* tBh = sBh + (size_t)(it % GSTAGES) * GTSZ;
        const __nv_bfloat16* tBl = sBl + (size_t)(it % GSTAGES) * GTSZ;

#pragma unroll
        for (int ks = 0; ks < 2; ks++) {
            const int kk = ks * 16;
            uint32_t afh[4][4], afl[4][4];
#pragma unroll
            for (int mt = 0; mt < 4; mt++) {
                int r = wm * 64 + mt * 16 + (lane & 15);
                int c = kk + ((lane >> 4) * 8);
                ldsm_x4(smem_u32(tAh + r * GP + c), afh[mt][0], afh[mt][1], afh[mt][2], afh[mt][3]);
                ldsm_x4(smem_u32(tAl + r * GP + c), afl[mt][0], afl[mt][1], afl[mt][2], afl[mt][3]);
            }
            uint32_t bfh[4][2], bfl[4][2];
#pragma unroll
            for (int p = 0; p < 2; p++) {
                int r = wn * 32 + p * 16 + (lane & 15);
                int c = kk + ((lane >> 4) * 8);
                uint32_t t0, t1, t2, t3;
                ldsm_x4(smem_u32(tBh + r * GP + c), t0, t1, t2, t3);
                bfh[2*p][0] = t0; bfh[2*p][1] = t2;
                bfh[2*p+1][0] = t1; bfh[2*p+1][1] = t3;
                ldsm_x4(smem_u32(tBl + r * GP + c), t0, t1, t2, t3);
                bfl[2*p][0] = t0; bfl[2*p][1] = t2;
                bfl[2*p+1][0] = t1; bfl[2*p+1][1] = t3;
            }
#pragma unroll
            for (int mt = 0; mt < 4; mt++)
#pragma unroll
                for (int nt = 0; nt < 4; nt++) {
                    mma16816(acc[mt][nt], afh[mt], bfh[nt]);
                    mma16816(acc[mt][nt], afh[mt], bfl[nt]);
                    mma16816(acc[mt][nt], afl[mt], bfh[nt]);
                }
        }
    }

    // epilogue
#pragma unroll
    for (int mt = 0; mt < 4; mt++)
#pragma unroll
        for (int nt = 0; nt < 4; nt++)
#pragma unroll
            for (int r = 0; r < 4; r++) {
                size_t row = m0 + wm * 64 + mt * 16 + (lane >> 2) + (r >> 1) * 8;
                int    col = n0 + wn * 32 + nt * 8 + (lane & 3) * 2 + (r & 1);
                float v = acc[mt][nt][r] + bias[col];
                if (mode == 0) {
                    C0[row * (size_t)N + col] = v;
                } else {
                    if (col < DMODEL) {
                        C0[row * (size_t)DMODEL + col] = v;
                    } else if (col < 2 * DMODEL) {
                        C1[row * (size_t)DMODEL + (col - DMODEL)] = v;
                    } else {
                        size_t idx = row * (size_t)DMODEL + (col - 2 * DMODEL);
                        C2[idx] = v;
                        __nv_bfloat16 hh = __float2bfloat16(v);
                        VH[idx] = hh;
                        VL[idx] = __float2bfloat16(v - __bfloat162float(hh));
                    }
                }
            }
}

// ---------------------------------------------------------------------------
// Batched scores GEMM: S[z; m, n] = sum_k Qn[z; m, k] * Kn[z; n, k]
// z = b*16+h; A/B are plane pairs with row stride DMODEL, col offset h*DHEAD.
// K = DHEAD = 128 (4 slabs). Same warp structure as gemm_planes.
// grid = (SEQ/128, SEQ/128, NBH)
// ---------------------------------------------------------------------------
__global__ __launch_bounds__(256, 1)
void gemm_scores(const __nv_bfloat16* __restrict__ Qh_g, const __nv_bfloat16* __restrict__ Ql_g,
                 const __nv_bfloat16* __restrict__ Kh_g, const __nv_bfloat16* __restrict__ Kl_g,
                 float* __restrict__ S)
{
    extern __shared__ __nv_bfloat16 smg[];
    __nv_bfloat16* sAh = smg;
    __nv_bfloat16* sAl = sAh + GSTAGES * GTSZ;
    __nv_bfloat16* sBh = sAl + GSTAGES * GTSZ;
    __nv_bfloat16* sBl = sBh + GSTAGES * GTSZ;

    const int tid  = threadIdx.x;
    const int wid  = tid >> 5;
    const int lane = tid & 31;
    const int wm   = wid >> 2;
    const int wn   = wid & 3;
    const int m0   = blockIdx.y * 128;
    const int n0   = blockIdx.x * 128;
    const int z    = blockIdx.z;
    const int b    = z >> 4;
    const int h    = z & 15;

    const size_t base = (size_t)b * SEQ * DMODEL + h * DHEAD;
    const __nv_bfloat16* Ah = Qh_g + base;
    const __nv_bfloat16* Al = Ql_g + base;
    const __nv_bfloat16* Bh = Kh_g + base;
    const __nv_bfloat16* Bl = Kl_g + base;
    float* Cz = S + (size_t)z * SEQ * SEQ;

    const int lrow = tid >> 1;
    const int lcol = (tid & 1) * 16;

    float acc[4][4][4];
#pragma unroll
    for (int i = 0; i < 4; i++)
#pragma unroll
        for (int j = 0; j < 4; j++)
#pragma unroll
            for (int r = 0; r < 4; r++) acc[i][j][r] = 0.f;

    const int iters = DHEAD / 32;   // 4

    auto load_tile = [&](int t, int st) {
        size_t ga = (size_t)(m0 + lrow) * DMODEL + t * 32 + lcol;
        size_t gb = (size_t)(n0 + lrow) * DMODEL + t * 32 + lcol;
        size_t so = (size_t)st * GTSZ + lrow * GP + lcol;
        cp16(sAh + so,     Ah + ga);
        cp16(sAh + so + 8, Ah + ga + 8);
        cp16(sAl + so,     Al + ga);
        cp16(sAl + so + 8, Al + ga + 8);
        cp16(sBh + so,     Bh + gb);
        cp16(sBh + so + 8, Bh + gb + 8);
        cp16(sBl + so,     Bl + gb);
        cp16(sBl + so + 8, Bl + gb + 8);
    };

    load_tile(0, 0); cp_commit();
    load_tile(1, 1); cp_commit();

    for (int it = 0; it < iters; ++it) {
        if (it + 2 < iters) cp_wait<1>(); else cp_wait<0>();
        __syncthreads();
        if (it + 2 < iters) { load_tile(it + 2, (it + 2) % GSTAGES); cp_commit(); }

        const __nv_bfloat16* tAh = sAh + (size_t)(it % GSTAGES) * GTSZ;
        const __nv_bfloat16* tAl = sAl + (size_t)(it % GSTAGES) * GTSZ;
        const __nv_bfloat16* tBh = sBh + (size_t)(it % GSTAGES) * GTSZ;
        const __nv_bfloat16* tBl = sBl + (size_t)(it % GSTAGES) * GTSZ;

#pragma unroll
        for (int ks = 0; ks < 2; ks++) {
            const int kk = ks * 16;
            uint32_t afh[4][4], afl[4][4];
#pragma unroll
            for (int mt = 0; mt < 4; mt++) {
                int r = wm * 64 + mt * 16 + (lane & 15);
                int c = kk + ((lane >> 4) * 8);
                ldsm_x4(smem_u32(tAh + r * GP + c), afh[mt][0], afh[mt][1], afh[mt][2], afh[mt][3]);
                ldsm_x4(smem_u32(tAl + r * GP + c), afl[mt][0], afl[mt][1], afl[mt][2], afl[mt][3]);
            }
            uint32_t bfh[4][2], bfl[4][2];
#pragma unroll
            for (int p = 0; p < 2; p++) {
                int r = wn * 32 + p * 16 + (lane & 15);
                int c = kk + ((lane >> 4) * 8);
                uint32_t t0, t1, t2, t3;
                ldsm_x4(smem_u32(tBh + r * GP + c), t0, t1, t2, t3);
                bfh[2*p][0] = t0; bfh[2*p][1] = t2;
                bfh[2*p+1][0] = t1; bfh[2*p+1][1] = t3;
                ldsm_x4(smem_u32(tBl + r * GP + c), t0, t1, t2, t3);
                bfl[2*p][0] = t0; bfl[2*p][1] = t2;
                bfl[2*p+1][0] = t1; bfl[2*p+1][1] = t3;
            }
#pragma unroll
            for (int mt = 0; mt < 4; mt++)
#pragma unroll
                for (int nt = 0; nt < 4; nt++) {
                    mma16816(acc[mt][nt], afh[mt], bfh[nt]);
                    mma16816(acc[mt][nt], afh[mt], bfl[nt]);
                    mma16816(acc[mt][nt], afl[mt], bfh[nt]);
                }
        }
    }

    // epilogue: fp32 scores, packed float2 stores
#pragma unroll
    for (int mt = 0; mt < 4; mt++)
#pragma unroll
        for (int nt = 0; nt < 4; nt++)
#pragma unroll
            for (int rr = 0; rr < 2; rr++) {
                size_t row = m0 + wm * 64 + mt * 16 + (lane >> 2) + rr * 8;
                int    col = n0 + wn * 32 + nt * 8 + (lane & 3) * 2;
                float2 v;
                v.x = acc[mt][nt][2*rr];
                v.y = acc[mt][nt][2*rr + 1];
                *(float2*)(Cz + row * SEQ + col) = v;
            }
}

// ---------------------------------------------------------------------------
// Exact row softmax: P[row,:] = softmax(S[row,:]) -> bf16 hi/lo planes
// (1/sum folded in). grid.x = NBH*SEQ rows, 256 threads, 8 elems/thread.
// ---------------------------------------------------------------------------
__global__ __launch_bounds__(256)
void softmax_rows(const float* __restrict__ S,
                  __nv_bfloat16* __restrict__ Ph, __nv_bfloat16* __restrict__ Pl)
{
    const size_t row = blockIdx.x;
    const float* src = S + row * SEQ;
    const int t = threadIdx.x;

    float v[8];
    float4 a0 = *(const float4*)(src + t * 8);
    float4 a1 = *(const float4*)(src + t * 8 + 4);
    v[0]=a0.x; v[1]=a0.y; v[2]=a0.z; v[3]=a0.w;
    v[4]=a1.x; v[5]=a1.y; v[6]=a1.z; v[7]=a1.w;

    __shared__ float red[8];
    // max
    float mx = v[0];
#pragma unroll
    for (int i = 1; i < 8; i++) mx = fmaxf(mx, v[i]);
#pragma unroll
    for (int o = 16; o > 0; o >>= 1) mx = fmaxf(mx, __shfl_xor_sync(0xffffffffu, mx, o));
    if ((t & 31) == 0) red[t >> 5] = mx;
    __syncthreads();
    float m = fmaxf(fmaxf(fmaxf(red[0], red[1]), fmaxf(red[2], red[3])),
                    fmaxf(fmaxf(red[4], red[5]), fmaxf(red[6], red[7])));
    __syncthreads();

    // exp + sum
    float s = 0.f;
#pragma unroll
    for (int i = 0; i < 8; i++) { v[i] = __expf(v[i] - m); s += v[i]; }
#pragma unroll
    for (int o = 16; o > 0; o >>= 1) s += __shfl_xor_sync(0xffffffffu, s, o);
    if ((t & 31) == 0) red[t >> 5] = s;
    __syncthreads();
    float tot = red[0]+red[1]+red[2]+red[3]+red[4]+red[5]+red[6]+red[7];
    float inv = 1.0f / tot;

    // write hi/lo planes (8 bf16 = one 16B store each)
    __nv_bfloat162 hh[4], ll[4];
#pragma unroll
    for (int i = 0; i < 4; i++) {
        float p0 = v[2*i] * inv, p1 = v[2*i+1] * inv;
        hh[i] = __floats2bfloat162_rn(p0, p1);
        float2 f = __bfloat1622float2(hh[i]);
        ll[i] = __floats2bfloat162_rn(p0 - f.x, p1 - f.y);
    }
    *(uint4*)(Ph + row * SEQ + t * 8) = *(uint4*)hh;
    *(uint4*)(Pl + row * SEQ + t * 8) = *(uint4*)ll;
}

// ---------------------------------------------------------------------------
// Batched PV GEMM: Z[z; m, d] = sum_k P[z; m, k] * V[z; k, d]
// A = P planes (row-major, ld=SEQ). B = V planes (k-major, ld=DMODEL, col off h*128)
// loaded with trans-ldsm. Output z planes (bf16 hi/lo). N = DHEAD = 128.
// grid = (SEQ/128, NBH). 3-stage cp.async.
// ---------------------------------------------------------------------------
#define VP 136
#define PVA (128 * GP)
#define PVB (32 * VP)

__global__ __launch_bounds__(256, 1)
void gemm_pv(const __nv_bfloat16* __restrict__ Ph_g, const __nv_bfloat16* __restrict__ Pl_g,
             const __nv_bfloat16* __restrict__ Vh_g, const __nv_bfloat16* __restrict__ Vl_g,
             __nv_bfloat16* __restrict__ ZH, __nv_bfloat16* __restrict__ ZL)
{
    extern __shared__ __nv_bfloat16 smp[];
    __nv_bfloat16* sAh = smp;
    __nv_bfloat16* sAl = sAh + GSTAGES * PVA;
    __nv_bfloat16* sBh = sAl + GSTAGES * PVA;
    __nv_bfloat16* sBl = sBh + GSTAGES * PVB;

    const int tid  = threadIdx.x;
    const int wid  = tid >> 5;
    const int lane = tid & 31;
    const int wm   = wid >> 2;       // 0..1 (64 q rows each)
    const int wn   = wid & 3;        // 0..3 (32 d cols each)
    const int m0   = blockIdx.x * 128;
    const int z    = blockIdx.y;
    const int b    = z >> 4;
    const int h    = z & 15;

    const __nv_bfloat16* Ah = Ph_g + (size_t)z * SEQ * SEQ;
    const __nv_bfloat16* Al = Pl_g + (size_t)z * SEQ * SEQ;
    const size_t vbase = (size_t)b * SEQ * DMODEL + h * DHEAD;

    const int lrow = tid >> 1;          // A load: 128 rows x 32 k
    const int lcol = (tid & 1) * 16;
    const int brow = tid >> 3;          // B load: 32 k-rows x 128 d
    const int bcol = (tid & 7) * 16;

    float acc[4][4][4];
#pragma unroll
    for (int i = 0; i < 4; i++)
#pragma unroll
        for (int j = 0; j < 4; j++)
#pragma unroll
            for (int r = 0; r < 4; r++) acc[i][j][r] = 0.f;

    const int iters = SEQ / 32;   // 64

    auto load_tile = [&](int t, int st) {
        size_t ga = (size_t)(m0 + lrow) * SEQ + t * 32 + lcol;
        size_t sa = (size_t)st * PVA + lrow * GP + lcol;
        cp16(sAh + sa,     Ah + ga);
        cp16(sAh + sa + 8, Ah + ga + 8);
        cp16(sAl + sa,     Al + ga);
        cp16(sAl + sa + 8, Al + ga + 8);
        size_t gb = vbase + (size_t)(t * 32 + brow) * DMODEL + bcol;
        size_t sb = (size_t)st * PVB + brow * VP + bcol;
        cp16(sBh + sb,     Vh_g + gb);
        cp16(sBh + sb + 8, Vh_g + gb + 8);
        cp16(sBl + sb,     Vl_g + gb);
        cp16(sBl + sb + 8, Vl_g + gb + 8);
    };

    load_tile(0, 0); cp_commit();
    load_tile(1, 1); cp_commit();

    for (int it = 0; it < iters; ++it) {
        if (it + 2 < iters) cp_wait<1>(); else cp_wait<0>();
        __syncthreads();
        if (it + 2 < iters) { load_tile(it + 2, (it + 2) % GSTAGES); cp_commit(); }

        const __nv_bfloat16* tAh = sAh + (size_t)(it % GSTAGES) * PVA;
        const __nv_bfloat16* tAl = sAl + (size_t)(it % GSTAGES) * PVA;
        const __nv_bfloat16* tBh = sBh + (size_t)(it % GSTAGES) * PVB;
        const __nv_bfloat16* tBl = sBl + (size_t)(it % GSTAGES) * PVB;

#pragma unroll
        for (int ks = 0; ks < 2; ks++) {
            const int kk = ks * 16;
            uint32_t afh[4][4], afl[4][4];
#pragma unroll
            for (int mt = 0; mt < 4; mt++) {
                int r = wm * 64 + mt * 16 + (lane & 15);
                int c = kk + ((lane >> 4) * 8);
                ldsm_x4(smem_u32(tAh + r * GP + c), afh[mt][0], afh[mt][1], afh[mt][2], afh[mt][3]);
                ldsm_x4(smem_u32(tAl + r * GP + c), afl[mt][0], afl[mt][1], afl[mt][2], afl[mt][3]);
            }
            // V fragments via trans ldsm: k-major tile [k][d]
            uint32_t bfh[4][2], bfl[4][2];
#pragma unroll
            for (int g = 0; g < 2; g++) {
                int r = kk + (lane & 15);
                int c = wn * 32 + g * 16 + ((lane >> 4) * 8);
                uint32_t t0, t1, t2, t3;
                ldsm_x4_t(smem_u32(tBh + r * VP + c), t0, t1, t2, t3);
                bfh[2*g][0] = t0; bfh[2*g][1] = t1;
                bfh[2*g+1][0] = t2; bfh[2*g+1][1] = t3;
                ldsm_x4_t(smem_u32(tBl + r * VP + c), t0, t1, t2, t3);
                bfl[2*g][0] = t0; bfl[2*g][1] = t1;
                bfl[2*g+1][0] = t2; bfl[2*g+1][1] = t3;
            }
#pragma unroll
            for (int mt = 0; mt < 4; mt++)
#pragma unroll
                for (int nt = 0; nt < 4; nt++) {
                    mma16816(acc[mt][nt], afh[mt], bfh[nt]);
                    mma16816(acc[mt][nt], afh[mt], bfl[nt]);
                    mma16816(acc[mt][nt], afl[mt], bfh[nt]);
                }
        }
    }

    // epilogue -> z planes (bf16 hi/lo), paired stores
#pragma unroll
    for (int mt = 0; mt < 4; mt++)
#pragma unroll
        for (int nt = 0; nt < 4; nt++)
#pragma unroll
            for (int rr = 0; rr < 2; rr++) {
                size_t row = (size_t)b * SEQ + m0 + wm * 64 + mt * 16 + (lane >> 2) + rr * 8;
                int    col = h * DHEAD + wn * 32 + nt * 8 + (lane & 3) * 2;
                float vx = acc[mt][nt][2*rr];
                float vy = acc[mt][nt][2*rr + 1];
                __nv_bfloat162 hh = __floats2bfloat162_rn(vx, vy);
                float2 f = __bfloat1622float2(hh);
                __nv_bfloat162 ll = __floats2bfloat162_rn(vx - f.x, vy - f.y);
                *(__nv_bfloat162*)(ZH + row * DMODEL + col) = hh;
                *(__nv_bfloat162*)(ZL + row * DMODEL + col) = ll;
            }
}

// ---------------------------------------------------------------------------
// RMS norm per head (128 elems) -> bf16 hi/lo planes.
// grid.x = MROWS*NHEADS, grid.y: 0 = q, 1 = k.
// ---------------------------------------------------------------------------
__global__ void rmsnorm_split(const float* __restrict__ qin, const float* __restrict__ kin,
                              __nv_bfloat16* __restrict__ qh, __nv_bfloat16* __restrict__ ql,
                              __nv_bfloat16* __restrict__ kh, __nv_bfloat16* __restrict__ kl,
                              const float* __restrict__ wq, const float* __restrict__ wk)
{
    const float* in;  __nv_bfloat16 *oh, *ol;  const float* w;
    if (blockIdx.y == 0) { in = qin; oh = qh; ol = ql; w = wq; }
    else                 { in = kin; oh = kh; ol = kl; w = wk; }

    size_t base = (size_t)blockIdx.x * DHEAD;
    int t = threadIdx.x;
    float v = in[base + t];
    float ss = v * v;
#pragma unroll
    for (int o = 16; o > 0; o >>= 1) ss += __shfl_xor_sync(0xffffffffu, ss, o);

    __shared__ float sred[4];
    int wrp = t >> 5, lane = t & 31;
    if (lane == 0) sred[wrp] = ss;
    __syncthreads();
    float tot = sred[0] + sred[1] + sred[2] + sred[3];
    float inv = rsqrtf(tot * (1.0f / DHEAD) + 1e-6f);
    float vn = v * inv * w[t];
    __nv_bfloat16 hh = __float2bfloat16(vn);
    oh[base + t] = hh;
    ol[base + t] = __float2bfloat16(vn - __bfloat162float(hh));
}

// ---------------------------------------------------------------------------
extern "C" void kernel_launch(void* const* d_in, const int* in_sizes, int n_in,
                              void* d_out, int out_size)
{
    const float* x     = (const float*)d_in[0];
    const float* W_qkv = (const float*)d_in[1];
    const float* b_qkv = (const float*)d_in[2];
    const float* W_o   = (const float*)d_in[3];
    const float* b_o   = (const float*)d_in[4];
    const float* wq    = (const float*)d_in[5];
    const float* wk    = (const float*)d_in[6];

    float* out   = (float*)d_out;                               // [4096,2048]
    float* k_out = out   + (size_t)MROWS * DMODEL;
    float* v_out = k_out + (size_t)MROWS * DMODEL;

    float *qPtr, *sPtr;
    __nv_bfloat16 *xh, *xl, *Wqh, *Wql, *Woh, *Wol;
    __nv_bfloat16 *qh, *ql, *kh, *kl, *vh, *vl, *zh, *zl, *ph, *pl;
    cudaGetSymbolAddress((void**)&qPtr, g_q);
    cudaGetSymbolAddress((void**)&sPtr, g_s);
    cudaGetSymbolAddress((void**)&xh,  g_xh);  cudaGetSymbolAddress((void**)&xl,  g_xl);
    cudaGetSymbolAddress((void**)&Wqh, g_Wqh); cudaGetSymbolAddress((void**)&Wql, g_Wql);
    cudaGetSymbolAddress((void**)&Woh, g_Woh); cudaGetSymbolAddress((void**)&Wol, g_Wol);
    cudaGetSymbolAddress((void**)&qh,  g_qh);  cudaGetSymbolAddress((void**)&ql,  g_ql);
    cudaGetSymbolAddress((void**)&kh,  g_kh);  cudaGetSymbolAddress((void**)&kl,  g_kl);
    cudaGetSymbolAddress((void**)&vh,  g_vh);  cudaGetSymbolAddress((void**)&vl,  g_vl);
    cudaGetSymbolAddress((void**)&zh,  g_zh);  cudaGetSymbolAddress((void**)&zl,  g_zl);
    cudaGetSymbolAddress((void**)&ph,  g_ph);  cudaGetSymbolAddress((void**)&pl,  g_pl);

    // 0) split inputs to bf16 hi/lo planes
    {
        int n4x = MROWS * DMODEL / 4;
        split_kernel<<<(n4x + 255) / 256, 256>>>(x, xh, xl, n4x);
        int n4q = NQKV * DMODEL / 4;
        split_kernel<<<(n4q + 255) / 256, 256>>>(W_qkv, Wqh, Wql, n4q);
        int n4o = DMODEL * DMODEL / 4;
        split_kernel<<<(n4o + 255) / 256, 256>>>(W_o, Woh, Wol, n4o);
    }

    int gemm_smem = 4 * GSTAGES * GTSZ * (int)sizeof(__nv_bfloat16);
    cudaFuncSetAttribute(gemm_planes, cudaFuncAttributeMaxDynamicSharedMemorySize, gemm_smem);
    cudaFuncSetAttribute(gemm_scores, cudaFuncAttributeMaxDynamicSharedMemorySize, gemm_smem);
    int pv_smem = 2 * GSTAGES * (PVA + PVB) * (int)sizeof(__nv_bfloat16);
    cudaFuncSetAttribute(gemm_pv, cudaFuncAttributeMaxDynamicSharedMemorySize, pv_smem);

    // 1) QKV projection
    {
        dim3 grid(NQKV / 128, MROWS / 128);
        gemm_planes<<<grid, 256, gemm_smem>>>(xh, xl, Wqh, Wql, b_qkv,
                                              qPtr, k_out, v_out, vh, vl,
                                              MROWS, NQKV, DMODEL, 1);
    }

    // 2) RMS norm q/k -> bf16 planes
    {
        dim3 grid(MROWS * NHEADS, 2);
        rmsnorm_split<<<grid, DHEAD>>>(qPtr, k_out, qh, ql, kh, kl, wq, wk);
    }

    // 3a) scores S = Qn Kn^T  (batched over b,h)
    {
        dim3 grid(SEQ / 128, SEQ / 128, NBH);
        gemm_scores<<<grid, 256, gemm_smem>>>(qh, ql, kh, kl, sPtr);
    }

    // 3b) exact row softmax -> P planes
    {
        softmax_rows<<<NBH * SEQ, 256>>>(sPtr, ph, pl);
    }

    // 3c) Z = P V  (batched over b,h) -> z planes
    {
        dim3 grid(SEQ / 128, NBH);
        gemm_pv<<<grid, 256, pv_smem>>>(ph, pl, vh, vl, zh, zl);
    }

    // 4) Output projection
    {
        dim3 grid(DMODEL / 128, MROWS / 128);
        gemm_planes<<<grid, 256, gemm_smem>>>(zh, zl, Woh, Wol, b_o,
                                              out, nullptr, nullptr, nullptr, nullptr,
                                              MROWS, DMODEL, DMODEL, 0);
    }
}

// round 10
// speedup vs baseline: 1.2543x; 1.2543x over previous
#include <cuda_runtime.h>
#include <cuda_bf16.h>
#include <math.h>
#include <stdint.h>

// Problem constants
#define BATCH 2
#define SEQ   2048
#define DMODEL 2048
#define NHEADS 16
#define DHEAD 128
#define MROWS (BATCH*SEQ)        // 4096
#define NQKV  (3*DMODEL)         // 6144

// ---------------------------------------------------------------------------
// Scratch (device globals; no runtime allocation allowed). bf16 hi/lo planes.
// ---------------------------------------------------------------------------
__device__ float g_q [ (size_t)MROWS * DMODEL ];                  // q pre-norm fp32
__device__ __nv_bfloat16 g_xh [ (size_t)MROWS * DMODEL ];
__device__ __nv_bfloat16 g_xl [ (size_t)MROWS * DMODEL ];
__device__ __nv_bfloat16 g_Wqh[ (size_t)NQKV  * DMODEL ];
__device__ __nv_bfloat16 g_Wql[ (size_t)NQKV  * DMODEL ];
__device__ __nv_bfloat16 g_Woh[ (size_t)DMODEL* DMODEL ];
__device__ __nv_bfloat16 g_Wol[ (size_t)DMODEL* DMODEL ];
__device__ __nv_bfloat16 g_qh [ (size_t)MROWS * DMODEL ];
__device__ __nv_bfloat16 g_ql [ (size_t)MROWS * DMODEL ];
__device__ __nv_bfloat16 g_kh [ (size_t)MROWS * DMODEL ];
__device__ __nv_bfloat16 g_kl [ (size_t)MROWS * DMODEL ];
__device__ __nv_bfloat16 g_vh [ (size_t)MROWS * DMODEL ];
__device__ __nv_bfloat16 g_vl [ (size_t)MROWS * DMODEL ];
__device__ __nv_bfloat16 g_zh [ (size_t)MROWS * DMODEL ];
__device__ __nv_bfloat16 g_zl [ (size_t)MROWS * DMODEL ];

// ---------------------------------------------------------------------------
// helpers
// ---------------------------------------------------------------------------
__device__ __forceinline__ uint32_t smem_u32(const void* p) {
    return (uint32_t)__cvta_generic_to_shared(p);
}
__device__ __forceinline__ void cp16(void* dst, const void* src) {
    asm volatile("cp.async.cg.shared.global [%0], [%1], 16;"
                 :: "r"(smem_u32(dst)), "l"(src));
}
__device__ __forceinline__ void cp_commit() { asm volatile("cp.async.commit_group;"); }
template<int N> __device__ __forceinline__ void cp_wait() {
    asm volatile("cp.async.wait_group %0;" :: "n"(N));
}
__device__ __forceinline__ void ldsm_x4(uint32_t addr, uint32_t& r0, uint32_t& r1,
                                        uint32_t& r2, uint32_t& r3) {
    asm volatile("ldmatrix.sync.aligned.m8n8.x4.shared.b16 {%0,%1,%2,%3}, [%4];"
                 : "=r"(r0), "=r"(r1), "=r"(r2), "=r"(r3) : "r"(addr));
}
__device__ __forceinline__ void ldsm_x4_t(uint32_t addr, uint32_t& r0, uint32_t& r1,
                                          uint32_t& r2, uint32_t& r3) {
    asm volatile("ldmatrix.sync.aligned.m8n8.x4.trans.shared.b16 {%0,%1,%2,%3}, [%4];"
                 : "=r"(r0), "=r"(r1), "=r"(r2), "=r"(r3) : "r"(addr));
}
__device__ __forceinline__ void mma16816(float* d, const uint32_t* a, const uint32_t* b) {
    asm volatile(
        "mma.sync.aligned.m16n8k16.row.col.f32.bf16.bf16.f32 "
        "{%0,%1,%2,%3}, {%4,%5,%6,%7}, {%8,%9}, {%0,%1,%2,%3};"
        : "+f"(d[0]), "+f"(d[1]), "+f"(d[2]), "+f"(d[3])
        : "r"(a[0]), "r"(a[1]), "r"(a[2]), "r"(a[3]), "r"(b[0]), "r"(b[1]));
}

// ---------------------------------------------------------------------------
// fp32 -> bf16 hi/lo plane split
// ---------------------------------------------------------------------------
__global__ void split_kernel(const float* __restrict__ in,
                             __nv_bfloat16* __restrict__ h,
                             __nv_bfloat16* __restrict__ l, int n4)
{
    int i = blockIdx.x * blockDim.x + threadIdx.x;
    if (i >= n4) return;
    float4 v = ((const float4*)in)[i];
    __nv_bfloat162 h0 = __floats2bfloat162_rn(v.x, v.y);
    __nv_bfloat162 h1 = __floats2bfloat162_rn(v.z, v.w);
    float2 f0 = __bfloat1622float2(h0);
    float2 f1 = __bfloat1622float2(h1);
    __nv_bfloat162 l0 = __floats2bfloat162_rn(v.x - f0.x, v.y - f0.y);
    __nv_bfloat162 l1 = __floats2bfloat162_rn(v.z - f1.x, v.w - f1.y);
    ((__nv_bfloat162*)h)[2*i]   = h0;
    ((__nv_bfloat162*)h)[2*i+1] = h1;
    ((__nv_bfloat162*)l)[2*i]   = l0;
    ((__nv_bfloat162*)l)[2*i+1] = l1;
}

// ---------------------------------------------------------------------------
// bf16x3 GEMM from planes, 2-stage cp.async pipeline, 2 CTAs/SM.
// C[m,n] = sum_k A[m,k]*B[n,k] + bias[n]
// BM=BN=128, BK=32, 256 threads = 8 warps (2m x 4n), warp tile 64x32.
// ---------------------------------------------------------------------------
#define GP 40
#define GSTAGES 2
#define GTSZ (128 * GP)

__global__ __launch_bounds__(256, 2)
void gemm_planes(const __nv_bfloat16* __restrict__ Ah, const __nv_bfloat16* __restrict__ Al,
                 const __nv_bfloat16* __restrict__ Bh, const __nv_bfloat16* __restrict__ Bl,
                 const float* __restrict__ bias,
                 float* __restrict__ C0, float* __restrict__ C1, float* __restrict__ C2,
                 __nv_bfloat16* __restrict__ VH, __nv_bfloat16* __restrict__ VL,
                 int M, int N, int K, int mode)
{
    extern __shared__ __nv_bfloat16 smg[];
    __nv_bfloat16* sAh = smg;
    __nv_bfloat16* sAl = sAh + GSTAGES * GTSZ;
    __nv_bfloat16* sBh = sAl + GSTAGES * GTSZ;
    __nv_bfloat16* sBl = sBh + GSTAGES * GTSZ;

    const int tid  = threadIdx.x;
    const int wid  = tid >> 5;
    const int lane = tid & 31;
    const int wm   = wid >> 2;
    const int wn   = wid & 3;
    const int m0   = blockIdx.y * 128;
    const int n0   = blockIdx.x * 128;

    const int lrow = tid >> 1;
    const int lcol = (tid & 1) * 16;

    float acc[4][4][4];
#pragma unroll
    for (int i = 0; i < 4; i++)
#pragma unroll
        for (int j = 0; j < 4; j++)
#pragma unroll
            for (int r = 0; r < 4; r++) acc[i][j][r] = 0.f;

    const int iters = K / 32;

    auto load_tile = [&](int t, int st) {
        size_t ga = (size_t)(m0 + lrow) * K + t * 32 + lcol;
        size_t gb = (size_t)(n0 + lrow) * K + t * 32 + lcol;
        size_t so = (size_t)st * GTSZ + lrow * GP + lcol;
        cp16(sAh + so,     Ah + ga);
        cp16(sAh + so + 8, Ah + ga + 8);
        cp16(sAl + so,     Al + ga);
        cp16(sAl + so + 8, Al + ga + 8);
        cp16(sBh + so,     Bh + gb);
        cp16(sBh + so + 8, Bh + gb + 8);
        cp16(sBl + so,     Bl + gb);
        cp16(sBl + so + 8, Bl + gb + 8);
    };

    load_tile(0, 0); cp_commit();

    for (int it = 0; it < iters; ++it) {
        __syncthreads();                 // WAR on the buffer we are about to fill
        if (it + 1 < iters) { load_tile(it + 1, (it + 1) & 1); cp_commit(); cp_wait<1>(); }
        else cp_wait<0>();
        __syncthreads();                 // tile `it` visible

        const __nv_bfloat16* tAh = sAh + (size_t)(it & 1) * GTSZ;
        const __nv_bfloat16* tAl = sAl + (size_t)(it & 1) * GTSZ;
        const __nv_bfloat16* tBh = sBh + (size_t)(it & 1) * GTSZ;
        const __nv_bfloat16* tBl = sBl + (size_t)(it & 1) * GTSZ;

#pragma unroll
        for (int ks = 0; ks < 2; ks++) {
            const int kk = ks * 16;
            uint32_t afh[4][4], afl[4][4];
#pragma unroll
            for (int mt = 0; mt < 4; mt++) {
                int r = wm * 64 + mt * 16 + (lane & 15);
                int c = kk + ((lane >> 4) * 8);
                ldsm_x4(smem_u32(tAh + r * GP + c), afh[mt][0], afh[mt][1], afh[mt][2], afh[mt][3]);
                ldsm_x4(smem_u32(tAl + r * GP + c), afl[mt][0], afl[mt][1], afl[mt][2], afl[mt][3]);
            }
            uint32_t bfh[4][2], bfl[4][2];
#pragma unroll
            for (int p = 0; p < 2; p++) {
                int r = wn * 32 + p * 16 + (lane & 15);
                int c = kk + ((lane >> 4) * 8);
                uint32_t t0, t1, t2, t3;
                ldsm_x4(smem_u32(tBh + r * GP + c), t0, t1, t2, t3);
                bfh[2*p][0] = t0; bfh[2*p][1] = t2;
                bfh[2*p+1][0] = t1; bfh[2*p+1][1] = t3;
                ldsm_x4(smem_u32(tBl + r * GP + c), t0, t1, t2, t3);
                bfl[2*p][0] = t0; bfl[2*p][1] = t2;
                bfl[2*p+1][0] = t1; bfl[2*p+1][1] = t3;
            }
#pragma unroll
            for (int mt = 0; mt < 4; mt++)
#pragma unroll
                for (int nt = 0; nt < 4; nt++) {
                    mma16816(acc[mt][nt], afh[mt], bfh[nt]);
                    mma16816(acc[mt][nt], afh[mt], bfl[nt]);
                    mma16816(acc[mt][nt], afl[mt], bfh[nt]);
                }
        }
    }

    // epilogue
#pragma unroll
    for (int mt = 0; mt < 4; mt++)
#pragma unroll
        for (int nt = 0; nt < 4; nt++)
#pragma unroll
            for (int r = 0; r < 4; r++) {
                size_t row = m0 + wm * 64 + mt * 16 + (lane >> 2) + (r >> 1) * 8;
                int    col = n0 + wn * 32 + nt * 8 + (lane & 3) * 2 + (r & 1);
                float v = acc[mt][nt][r] + bias[col];
                if (mode == 0) {
                    C0[row * (size_t)N + col] = v;
                } else {
                    if (col < DMODEL) {
                        C0[row * (size_t)DMODEL + col] = v;
                    } else if (col < 2 * DMODEL) {
                        C1[row * (size_t)DMODEL + (col - DMODEL)] = v;
                    } else {
                        size_t idx = row * (size_t)DMODEL + (col - 2 * DMODEL);
                        C2[idx] = v;
                        __nv_bfloat16 hh = __float2bfloat16(v);
                        VH[idx] = hh;
                        VL[idx] = __float2bfloat16(v - __bfloat162float(hh));
                    }
                }
            }
}

// ---------------------------------------------------------------------------
// RMS norm per head (128 elems) -> bf16 hi/lo planes.
// ---------------------------------------------------------------------------
__global__ void rmsnorm_split(const float* __restrict__ qin, const float* __restrict__ kin,
                              __nv_bfloat16* __restrict__ qh, __nv_bfloat16* __restrict__ ql,
                              __nv_bfloat16* __restrict__ kh, __nv_bfloat16* __restrict__ kl,
                              const float* __restrict__ wq, const float* __restrict__ wk)
{
    const float* in;  __nv_bfloat16 *oh, *ol;  const float* w;
    if (blockIdx.y == 0) { in = qin; oh = qh; ol = ql; w = wq; }
    else                 { in = kin; oh = kh; ol = kl; w = wk; }

    size_t base = (size_t)blockIdx.x * DHEAD;
    int t = threadIdx.x;
    float v = in[base + t];
    float ss = v * v;
#pragma unroll
    for (int o = 16; o > 0; o >>= 1) ss += __shfl_xor_sync(0xffffffffu, ss, o);

    __shared__ float sred[4];
    int wrp = t >> 5, lane = t & 31;
    if (lane == 0) sred[wrp] = ss;
    __syncthreads();
    float tot = sred[0] + sred[1] + sred[2] + sred[3];
    float inv = rsqrtf(tot * (1.0f / DHEAD) + 1e-6f);
    float vn = v * inv * w[t];
    __nv_bfloat16 hh = __float2bfloat16(vn);
    oh[base + t] = hh;
    ol[base + t] = __float2bfloat16(vn - __bfloat162float(hh));
}

// ---------------------------------------------------------------------------
// Fused flash attention (bf16x3, fp32 softmax), 2 CTAs/SM.
// 128 threads = 4 warps; Q tile 64 rows (16/warp); K/V tiles 32 keys,
// double-buffered via cp.async. smem = 104448 B -> two CTAs resident.
// grid = (SEQ/64, NHEADS, BATCH)
// ---------------------------------------------------------------------------
#define QP 136
#define KVK 32
#define KVT (KVK * QP)

__global__ __launch_bounds__(128, 2)
void attn_tc3(const __nv_bfloat16* __restrict__ Qh_g, const __nv_bfloat16* __restrict__ Ql_g,
              const __nv_bfloat16* __restrict__ Kh_g, const __nv_bfloat16* __restrict__ Kl_g,
              const __nv_bfloat16* __restrict__ Vh_g, const __nv_bfloat16* __restrict__ Vl_g,
              __nv_bfloat16* __restrict__ ZH, __nv_bfloat16* __restrict__ ZL)
{
    extern __shared__ __nv_bfloat16 smx[];
    __nv_bfloat16* Qh = smx;                 // 64*QP
    __nv_bfloat16* Ql = Qh + 64 * QP;
    __nv_bfloat16* Kh = Ql + 64 * QP;        // 2 stages x 32*QP each
    __nv_bfloat16* Kl = Kh + 2 * KVT;
    __nv_bfloat16* Vh = Kl + 2 * KVT;
    __nv_bfloat16* Vl = Vh + 2 * KVT;

    const int tid  = threadIdx.x;
    const int wid  = tid >> 5;               // 0..3
    const int lane = tid & 31;
    const int b  = blockIdx.z;
    const int h  = blockIdx.y;
    const int q0 = blockIdx.x * 64;
    const size_t rowBase = (size_t)b * SEQ;
    const int colBase = h * DHEAD;

    // Q tile: 64 rows x 128 cols x 2 planes
    {
        int r = tid >> 1;                    // 0..63
        int c0 = (tid & 1) * 64;
        size_t g = (rowBase + q0 + r) * DMODEL + colBase + c0;
#pragma unroll
        for (int i = 0; i < 8; i++) {
            *(uint4*)(Qh + r * QP + c0 + i * 8) = *(const uint4*)(Qh_g + g + i * 8);
            *(uint4*)(Ql + r * QP + c0 + i * 8) = *(const uint4*)(Ql_g + g + i * 8);
        }
    }

    auto load_tile = [&](int jt, int st) {
        int kr0 = jt * KVK;
#pragma unroll
        for (int i = 0; i < 4; i++) {
            int c = i * 128 + tid;           // 0..511
            int r = c >> 4, col = (c & 15) * 8;
            size_t g = (rowBase + kr0 + r) * DMODEL + colBase + col;
            size_t s = (size_t)st * KVT + r * QP + col;
            cp16(Kh + s, Kh_g + g);
            cp16(Kl + s, Kl_g + g);
            cp16(Vh + s, Vh_g + g);
            cp16(Vl + s, Vl_g + g);
        }
    };

    float m_i[2] = {-1e30f, -1e30f};
    float l_i[2] = {0.f, 0.f};
    float o[16][4];
#pragma unroll
    for (int i = 0; i < 16; i++)
#pragma unroll
        for (int r = 0; r < 4; r++) o[i][r] = 0.f;

    load_tile(0, 0); cp_commit();

    const int NT = SEQ / KVK;                // 64 tiles
    for (int jt = 0; jt < NT; jt++) {
        __syncthreads();                     // WAR: buffer (jt+1)&1 free
        if (jt + 1 < NT) { load_tile(jt + 1, (jt + 1) & 1); cp_commit(); cp_wait<1>(); }
        else cp_wait<0>();
        __syncthreads();                     // tile jt visible (and Q on jt=0)

        const size_t st = (size_t)(jt & 1) * KVT;

        // ---- S = Q K^T : warp rows [16*wid,16*wid+16) x 32 keys
        float s[4][4];
#pragma unroll
        for (int i = 0; i < 4; i++)
#pragma unroll
            for (int r = 0; r < 4; r++) s[i][r] = 0.f;

#pragma unroll
        for (int ks = 0; ks < 8; ks++) {
            uint32_t ah[4], al[4];
            {
                int r = wid * 16 + (lane & 15);
                int c = ks * 16 + ((lane >> 4) * 8);
                ldsm_x4(smem_u32(Qh + r * QP + c), ah[0], ah[1], ah[2], ah[3]);
                ldsm_x4(smem_u32(Ql + r * QP + c), al[0], al[1], al[2], al[3]);
            }
#pragma unroll
            for (int p = 0; p < 2; p++) {
                int r = p * 16 + (lane & 15);
                int c = ks * 16 + ((lane >> 4) * 8);
                uint32_t t0, t1, t2, t3;
                uint32_t bh0[2], bh1[2], bl0[2], bl1[2];
                ldsm_x4(smem_u32(Kh + st + r * QP + c), t0, t1, t2, t3);
                bh0[0] = t0; bh0[1] = t2; bh1[0] = t1; bh1[1] = t3;
                ldsm_x4(smem_u32(Kl + st + r * QP + c), t0, t1, t2, t3);
                bl0[0] = t0; bl0[1] = t2; bl1[0] = t1; bl1[1] = t3;
                mma16816(s[2*p],   ah, bh0);
                mma16816(s[2*p],   ah, bl0);
                mma16816(s[2*p],   al, bh0);
                mma16816(s[2*p+1], ah, bh1);
                mma16816(s[2*p+1], ah, bl1);
                mma16816(s[2*p+1], al, bh1);
            }
        }

        // ---- online softmax (rows in quads: lanes xor1/xor2)
#pragma unroll
        for (int half = 0; half < 2; half++) {
            float rmax = -1e30f;
#pragma unroll
            for (int nt = 0; nt < 4; nt++)
                rmax = fmaxf(rmax, fmaxf(s[nt][2*half], s[nt][2*half + 1]));
            rmax = fmaxf(rmax, __shfl_xor_sync(0xffffffffu, rmax, 1));
            rmax = fmaxf(rmax, __shfl_xor_sync(0xffffffffu, rmax, 2));
            float mnew = fmaxf(m_i[half], rmax);
            float scale = __expf(m_i[half] - mnew);
            float rs = 0.f;
#pragma unroll
            for (int nt = 0; nt < 4; nt++) {
                float p0 = __expf(s[nt][2*half]     - mnew);
                float p1 = __expf(s[nt][2*half + 1] - mnew);
                s[nt][2*half]     = p0;
                s[nt][2*half + 1] = p1;
                rs += p0 + p1;
            }
            rs += __shfl_xor_sync(0xffffffffu, rs, 1);
            rs += __shfl_xor_sync(0xffffffffu, rs, 2);
            l_i[half] = l_i[half] * scale + rs;
            m_i[half] = mnew;
#pragma unroll
            for (int nt = 0; nt < 16; nt++) {
                o[nt][2*half]     *= scale;
                o[nt][2*half + 1] *= scale;
            }
        }

        // ---- O += P V (P fragments built in registers)
#pragma unroll
        for (int kk = 0; kk < 2; kk++) {
            uint32_t pah[4], pal[4];
            {
                float v0 = s[2*kk][0],   v1 = s[2*kk][1],   v2 = s[2*kk][2],   v3 = s[2*kk][3];
                float w0 = s[2*kk+1][0], w1 = s[2*kk+1][1], w2 = s[2*kk+1][2], w3 = s[2*kk+1][3];
                __nv_bfloat162 hx;
                float2 f;
                hx = __floats2bfloat162_rn(v0, v1); f = __bfloat1622float2(hx);
                pah[0] = *(uint32_t*)&hx; { __nv_bfloat162 t = __floats2bfloat162_rn(v0 - f.x, v1 - f.y); pal[0] = *(uint32_t*)&t; }
                hx = __floats2bfloat162_rn(v2, v3); f = __bfloat1622float2(hx);
                pah[1] = *(uint32_t*)&hx; { __nv_bfloat162 t = __floats2bfloat162_rn(v2 - f.x, v3 - f.y); pal[1] = *(uint32_t*)&t; }
                hx = __floats2bfloat162_rn(w0, w1); f = __bfloat1622float2(hx);
                pah[2] = *(uint32_t*)&hx; { __nv_bfloat162 t = __floats2bfloat162_rn(w0 - f.x, w1 - f.y); pal[2] = *(uint32_t*)&t; }
                hx = __floats2bfloat162_rn(w2, w3); f = __bfloat1622float2(hx);
                pah[3] = *(uint32_t*)&hx; { __nv_bfloat162 t = __floats2bfloat162_rn(w2 - f.x, w3 - f.y); pal[3] = *(uint32_t*)&t; }
            }
#pragma unroll
            for (int p = 0; p < 8; p++) {
                int r = kk * 16 + (lane & 15);
                int c = p * 16 + ((lane >> 4) * 8);
                uint32_t vh0[2], vh1[2], vl0[2], vl1[2];
                uint32_t t0, t1, t2, t3;
                ldsm_x4_t(smem_u32(Vh + st + r * QP + c), t0, t1, t2, t3);
                vh0[0] = t0; vh0[1] = t1; vh1[0] = t2; vh1[1] = t3;
                ldsm_x4_t(smem_u32(Vl + st + r * QP + c), t0, t1, t2, t3);
                vl0[0] = t0; vl0[1] = t1; vl1[0] = t2; vl1[1] = t3;
                mma16816(o[2*p],   pah, vh0);
                mma16816(o[2*p],   pah, vl0);
                mma16816(o[2*p],   pal, vh0);
                mma16816(o[2*p+1], pah, vh1);
                mma16816(o[2*p+1], pah, vl1);
                mma16816(o[2*p+1], pal, vh1);
            }
        }
    }

    // finalize -> z planes
    float invl[2] = {1.f / l_i[0], 1.f / l_i[1]};
#pragma unroll
    for (int half = 0; half < 2; half++) {
        size_t row = rowBase + q0 + wid * 16 + (lane >> 2) + half * 8;
#pragma unroll
        for (int nt = 0; nt < 16; nt++) {
            int col = colBase + nt * 8 + (lane & 3) * 2;
            float vx = o[nt][2*half]     * invl[half];
            float vy = o[nt][2*half + 1] * invl[half];
            __nv_bfloat162 hh = __floats2bfloat162_rn(vx, vy);
            float2 f = __bfloat1622float2(hh);
            __nv_bfloat162 ll = __floats2bfloat162_rn(vx - f.x, vy - f.y);
            *(__nv_bfloat162*)(ZH + row * DMODEL + col) = hh;
            *(__nv_bfloat162*)(ZL + row * DMODEL + col) = ll;
        }
    }
}

// ---------------------------------------------------------------------------
extern "C" void kernel_launch(void* const* d_in, const int* in_sizes, int n_in,
                              void* d_out, int out_size)
{
    const float* x     = (const float*)d_in[0];
    const float* W_qkv = (const float*)d_in[1];
    const float* b_qkv = (const float*)d_in[2];
    const float* W_o   = (const float*)d_in[3];
    const float* b_o   = (const float*)d_in[4];
    const float* wq    = (const float*)d_in[5];
    const float* wk    = (const float*)d_in[6];

    float* out   = (float*)d_out;                               // [4096,2048]
    float* k_out = out   + (size_t)MROWS * DMODEL;
    float* v_out = k_out + (size_t)MROWS * DMODEL;

    float* qPtr;
    __nv_bfloat16 *xh, *xl, *Wqh, *Wql, *Woh, *Wol;
    __nv_bfloat16 *qh, *ql, *kh, *kl, *vh, *vl, *zh, *zl;
    cudaGetSymbolAddress((void**)&qPtr, g_q);
    cudaGetSymbolAddress((void**)&xh,  g_xh);  cudaGetSymbolAddress((void**)&xl,  g_xl);
    cudaGetSymbolAddress((void**)&Wqh, g_Wqh); cudaGetSymbolAddress((void**)&Wql, g_Wql);
    cudaGetSymbolAddress((void**)&Woh, g_Woh); cudaGetSymbolAddress((void**)&Wol, g_Wol);
    cudaGetSymbolAddress((void**)&qh,  g_qh);  cudaGetSymbolAddress((void**)&ql,  g_ql);
    cudaGetSymbolAddress((void**)&kh,  g_kh);  cudaGetSymbolAddress((void**)&kl,  g_kl);
    cudaGetSymbolAddress((void**)&vh,  g_vh);  cudaGetSymbolAddress((void**)&vl,  g_vl);
    cudaGetSymbolAddress((void**)&zh,  g_zh);  cudaGetSymbolAddress((void**)&zl,  g_zl);

    // 0) split inputs to bf16 hi/lo planes
    {
        int n4x = MROWS * DMODEL / 4;
        split_kernel<<<(n4x + 255) / 256, 256>>>(x, xh, xl, n4x);
        int n4q = NQKV * DMODEL / 4;
        split_kernel<<<(n4q + 255) / 256, 256>>>(W_qkv, Wqh, Wql, n4q);
        int n4o = DMODEL * DMODEL / 4;
        split_kernel<<<(n4o + 255) / 256, 256>>>(W_o, Woh, Wol, n4o);
    }

    int gemm_smem = 4 * GSTAGES * GTSZ * (int)sizeof(__nv_bfloat16);   // 80 KB
    cudaFuncSetAttribute(gemm_planes, cudaFuncAttributeMaxDynamicSharedMemorySize, gemm_smem);

    // 1) QKV projection
    {
        dim3 grid(NQKV / 128, MROWS / 128);
        gemm_planes<<<grid, 256, gemm_smem>>>(xh, xl, Wqh, Wql, b_qkv,
                                              qPtr, k_out, v_out, vh, vl,
                                              MROWS, NQKV, DMODEL, 1);
    }

    // 2) RMS norm q/k -> bf16 planes
    {
        dim3 grid(MROWS * NHEADS, 2);
        rmsnorm_split<<<grid, DHEAD>>>(qPtr, k_out, qh, ql, kh, kl, wq, wk);
    }

    // 3) Attention -> z planes (2 CTAs/SM)
    {
        int smem = (2 * 64 * QP + 8 * KVT) * (int)sizeof(__nv_bfloat16);  // 104448 B
        cudaFuncSetAttribute(attn_tc3, cudaFuncAttributeMaxDynamicSharedMemorySize, smem);
        dim3 grid(SEQ / 64, NHEADS, BATCH);
        attn_tc3<<<grid, 128, smem>>>(qh, ql, kh, kl, vh, vl, zh, zl);
    }

    // 4) Output projection
    {
        dim3 grid(DMODEL / 128, MROWS / 128);
        gemm_planes<<<grid, 256, gemm_smem>>>(zh, zl, Woh, Wol, b_o,
                                              out, nullptr, nullptr, nullptr, nullptr,
                                              MROWS, DMODEL, DMODEL, 0);
    }
}